// round 16
// baseline (speedup 1.0000x reference)
#include <cuda_runtime.h>
#include <cstdint>

// Problem constants
#define BB 8
#define LL 4096
#define DD 768
#define NROWS (BB * LL)        // 32768
#define NB 736                 // 8 x 92; co-resident at 5 blocks/SM (144*5+4*4 >= 736)
#define NT 256                 // 8 warps
#define BPB 92                 // blocks per batch
#define WPB (BPB * 8)          // 736 warps per batch

// Scratch (device globals). No cache hints (R2/R3/R8 failed).
__device__ __align__(16) float g_part[NB * DD];    // per-block column partials (2.2 MB)
__device__ __align__(16) float g_sum[BB * DD];     // full column sums
__device__ float g_sqpart[BB * 3];                 // per-colgroup sum of squares
__device__ unsigned g_arrive = 0;                  // epoch barrier (monotone, replay-safe)

__device__ __forceinline__ void grid_barrier() {
    __syncthreads();
    if (threadIdx.x == 0) {
        __threadfence();
        unsigned old = atomicAdd(&g_arrive, 1u);
        unsigned target = (old / NB + 1u) * NB;
        while ((int)(*(volatile unsigned*)&g_arrive - target) < 0)
            __nanosleep(32);
    }
    __syncthreads();
}

// 5 blocks/SM: ptxas must keep regs <= 51 -> 40 warps/SM co-resident.
__global__ __launch_bounds__(NT, 5) void fused_kernel(const float* __restrict__ x,
                                                      const float* __restrict__ alpha,
                                                      float* __restrict__ out) {
    // 24 KB: phase 1 = per-warp column partials; phase 3 = all 8 sum_b rows.
    __shared__ float4 s_buf[8][DD / 4];
    __shared__ float red[NT];
    __shared__ float s_coef[BB];

    const int tid  = threadIdx.x;
    const int bid  = blockIdx.x;
    const int warp = tid >> 5;
    const int lane = tid & 31;

    const int b  = bid / BPB;                     // batch, fixed per block
    const int w  = (bid % BPB) * 8 + warp;        // warp-in-batch, 0..735
    const int r0 = (w * LL) / WPB;                // contiguous window [r0, r1)
    const int r1 = ((w + 1) * LL) / WPB;          // 5 or 6 rows
    const float* xb = x + ((size_t)b << 12) * DD;

    // ---- Phase 1: column sums over the warp's consecutive rows. Two half-row
    // steps (3 float4 live) keep registers under the 51-reg cap. ----
    {
        float4 acc[6];
#pragma unroll
        for (int i = 0; i < 6; i++) acc[i] = make_float4(0.f, 0.f, 0.f, 0.f);
        const float4* xp = reinterpret_cast<const float4*>(xb + (size_t)r0 * DD) + lane;
        for (int k = 0; k < r1 - r0; k++) {
            const float4* rp = xp + (size_t)k * (DD / 4);
#pragma unroll
            for (int h = 0; h < 2; h++) {
                float4 v0 = rp[(h * 3 + 0) * 32];
                float4 v1 = rp[(h * 3 + 1) * 32];
                float4 v2 = rp[(h * 3 + 2) * 32];
                acc[h*3+0].x += v0.x; acc[h*3+0].y += v0.y; acc[h*3+0].z += v0.z; acc[h*3+0].w += v0.w;
                acc[h*3+1].x += v1.x; acc[h*3+1].y += v1.y; acc[h*3+1].z += v1.z; acc[h*3+1].w += v1.w;
                acc[h*3+2].x += v2.x; acc[h*3+2].y += v2.y; acc[h*3+2].z += v2.z; acc[h*3+2].w += v2.w;
            }
        }
#pragma unroll
        for (int i = 0; i < 6; i++) s_buf[warp][lane + i * 32] = acc[i];
        __syncthreads();

        const float* sa = reinterpret_cast<const float*>(s_buf);
#pragma unroll
        for (int k = 0; k < 3; k++) {
            const int col = tid + k * NT;
            float s = ((sa[0 * DD + col] + sa[1 * DD + col])
                     + (sa[2 * DD + col] + sa[3 * DD + col]))
                    + ((sa[4 * DD + col] + sa[5 * DD + col])
                     + (sa[6 * DD + col] + sa[7 * DD + col]));
            g_part[(size_t)bid * DD + col] = s;
        }
    }

    grid_barrier();

    // ---- Phase 2: 24 blocks (8 batches x 3 col-groups of 256). Reduce the 92
    // block-partials per batch; per-group sum of squares (~2.2 MB, L2). ----
    if (bid < 24) {
        const int pb = bid / 3;
        const int g  = bid % 3;
        const int col = g * 256 + tid;

        const float* p = g_part + (size_t)pb * BPB * DD + col;
        float a0 = 0.f, a1 = 0.f;
#pragma unroll 4
        for (int k = 0; k < BPB; k += 2) {
            a0 += p[(size_t)(k + 0) * DD];
            a1 += p[(size_t)(k + 1) * DD];
        }
        const float s = a0 + a1;
        g_sum[pb * DD + col] = s;

        red[tid] = s * s;
        __syncthreads();
        if (tid < 128) red[tid] += red[tid + 128];
        __syncthreads();
        if (tid < 64) red[tid] += red[tid + 64];
        __syncthreads();
        if (tid < 32) {
            float v = red[tid] + red[tid + 32];
#pragma unroll
            for (int off = 16; off > 0; off >>= 1)
                v += __shfl_xor_sync(0xFFFFFFFFu, v, off);
            if (tid == 0) g_sqpart[pb * 3 + g] = v;
        }
    }

    grid_barrier();

    // ---- Phase 3: finalize over the same windows, rows DESCENDING, sync-free
    // after one preload. Two passes per row: A) stream x through the dot
    // (no registers held), B) reload x (L1/L2-hot) and store. All warps sit at
    // the same fractional window position -> coherent descending frontier ->
    // second x read mostly L2 hits (~75-85 MB saved; R6, R9-R11, R15 data).
    {
#pragma unroll
        for (int k = 0; k < 6; k++) {
            const int idx = tid + k * NT;               // 0..1535
            reinterpret_cast<float4*>(s_buf)[idx] =
                reinterpret_cast<const float4*>(g_sum)[idx];
        }
        if (tid < BB) {
            const float sq = g_sqpart[tid * 3 + 0] + g_sqpart[tid * 3 + 1]
                           + g_sqpart[tid * 3 + 2];
            const double denom = (double)DD * (double)DD
                               * (double)LL * (double)LL * (double)LL * (double)LL;
            s_coef[tid] = (float)((double)sq / denom);
        }
        __syncthreads();   // the only phase-3 sync

        const float coef = s_coef[b];
        float* ob = out + ((size_t)b << 12) * DD;

        for (int k = r1 - r0 - 1; k >= 0; k--) {
            const int l = r0 + k;                       // descending in window
            const float4* xp = reinterpret_cast<const float4*>(xb + (size_t)l * DD) + lane;

            // Pass A: dot(x_row, sum_b); values streamed, not held.
            float dot = 0.f;
#pragma unroll
            for (int i = 0; i < 6; i++) {
                float4 v = xp[i * 32];
                float4 m = s_buf[b][lane + i * 32];
                dot += v.x * m.x + v.y * m.y + v.z * m.z + v.w * m.w;
            }
#pragma unroll
            for (int off = 16; off > 0; off >>= 1)
                dot += __shfl_xor_sync(0xFFFFFFFFu, dot, off);

            const float y2 = dot * coef;
            const float a  = alpha[l];

            // Pass B: reload (L1/L2-hot) and write.
            float4* op = reinterpret_cast<float4*>(ob + (size_t)l * DD) + lane;
#pragma unroll
            for (int i = 0; i < 6; i++) {
                float4 v = xp[i * 32];
                float4 o;
                o.x = a + y2 * v.x;
                o.y = a + y2 * v.y;
                o.z = a + y2 * v.z;
                o.w = a + y2 * v.w;
                op[i * 32] = o;
            }
        }
    }
}

extern "C" void kernel_launch(void* const* d_in, const int* in_sizes, int n_in,
                              void* d_out, int out_size) {
    const float* x     = (const float*)d_in[0];   // [8, 4096, 768] f32
    const float* alpha = (const float*)d_in[1];   // [4096, 1] f32
    float* out = (float*)d_out;                   // [8, 4096, 768] f32

    fused_kernel<<<NB, NT>>>(x, alpha, out);
}

// round 17
// speedup vs baseline: 1.0987x; 1.0987x over previous
#include <cuda_runtime.h>
#include <cstdint>

// Problem constants
#define BB 8
#define LL 4096
#define DD 768
#define NROWS (BB * LL)        // 32768
#define NB 740                 // 148 SMs x 5 blocks: EVERY SM holds exactly 5
#define NT 192                 // 6 warps; 192 = 768/4 float4 columns exactly
#define WPBATCH 555            // phase-3 warps per batch (740*6/8)

// Scratch (device globals). No cache hints (R2/R3/R8 failed).
__device__ __align__(16) float g_part[NB * DD];    // per-block column partials (2.2 MB)
__device__ __align__(16) float g_sum[BB * DD];     // full column sums
__device__ float g_sqpart[BB * 4];                 // per-colgroup sum of squares
__device__ unsigned g_arrive = 0;                  // epoch barrier (monotone, replay-safe)

__device__ __forceinline__ void grid_barrier() {
    __syncthreads();
    if (threadIdx.x == 0) {
        __threadfence();
        unsigned old = atomicAdd(&g_arrive, 1u);
        unsigned target = (old / NB + 1u) * NB;
        while ((int)(*(volatile unsigned*)&g_arrive - target) < 0)
            __nanosleep(32);
    }
    __syncthreads();
}

// Batch-aligned phase-1 block mapping: batches 0-3 get 93 blocks, 4-7 get 92.
__device__ __forceinline__ void p1_map(int bid, int& b, int& i, int& cntB) {
    if (bid < 4 * 93) { b = bid / 93; i = bid - b * 93; cntB = 93; }
    else { int r = bid - 372; b = 4 + r / 92; i = r - (b - 4) * 92; cntB = 92; }
}

__global__ __launch_bounds__(NT, 5) void fused_kernel(const float* __restrict__ x,
                                                      const float* __restrict__ alpha,
                                                      float* __restrict__ out) {
    // 24 KB: phase 3 holds all 8 sum_b rows. (Phase 1 doesn't need smem.)
    __shared__ float4 s_buf[8][DD / 4];
    __shared__ float red[NT];
    __shared__ float s_coef[BB];

    const int tid  = threadIdx.x;
    const int bid  = blockIdx.x;
    const int warp = tid >> 5;
    const int lane = tid & 31;

    // ---- Phase 1: column sums, R5's proven 5.5 TB/s pattern.
    // Thread t owns float4-column t; contiguous batch-aligned window of 44-45
    // rows; 4-batched loads (MLP 4, ~34 regs). Ascending sweep.
    {
        int b, i, cntB;
        p1_map(bid, b, i, cntB);
        const int r0 = (i * LL) / cntB;
        const int r1 = ((i + 1) * LL) / cntB;
        const int n  = r1 - r0;

        const float4* xp = reinterpret_cast<const float4*>(x) +
                           ((size_t)b * LL + r0) * (DD / 4) + tid;
        float4 a0 = make_float4(0.f, 0.f, 0.f, 0.f);
        float4 a1 = make_float4(0.f, 0.f, 0.f, 0.f);
        float4 a2 = make_float4(0.f, 0.f, 0.f, 0.f);
        float4 a3 = make_float4(0.f, 0.f, 0.f, 0.f);
        int k = 0;
        for (; k + 4 <= n; k += 4) {
            float4 v0 = xp[(size_t)(k + 0) * (DD / 4)];
            float4 v1 = xp[(size_t)(k + 1) * (DD / 4)];
            float4 v2 = xp[(size_t)(k + 2) * (DD / 4)];
            float4 v3 = xp[(size_t)(k + 3) * (DD / 4)];
            a0.x += v0.x; a0.y += v0.y; a0.z += v0.z; a0.w += v0.w;
            a1.x += v1.x; a1.y += v1.y; a1.z += v1.z; a1.w += v1.w;
            a2.x += v2.x; a2.y += v2.y; a2.z += v2.z; a2.w += v2.w;
            a3.x += v3.x; a3.y += v3.y; a3.z += v3.z; a3.w += v3.w;
        }
        for (; k < n; k++) {
            float4 v = xp[(size_t)k * (DD / 4)];
            a0.x += v.x; a0.y += v.y; a0.z += v.z; a0.w += v.w;
        }
        float4 s = make_float4((a0.x + a1.x) + (a2.x + a3.x),
                               (a0.y + a1.y) + (a2.y + a3.y),
                               (a0.z + a1.z) + (a2.z + a3.z),
                               (a0.w + a1.w) + (a2.w + a3.w));
        reinterpret_cast<float4*>(g_part)[(size_t)bid * (DD / 4) + tid] = s;
    }

    grid_barrier();

    // ---- Phase 2: 32 blocks (8 batches x 4 col-groups of 192). Reduce each
    // batch's 92/93 block-partials; per-group sum of squares (~2.2 MB, L2). ----
    if (bid < 32) {
        const int b = bid >> 2;
        const int g = bid & 3;
        const int col = g * 192 + tid;
        const int start = (b < 4) ? b * 93 : 372 + (b - 4) * 92;
        const int cnt   = (b < 4) ? 93 : 92;

        const float* p = g_part + (size_t)start * DD + col;
        float a0 = 0.f, a1 = 0.f;
        int k = 0;
        for (; k + 2 <= cnt; k += 2) {
            a0 += p[(size_t)(k + 0) * DD];
            a1 += p[(size_t)(k + 1) * DD];
        }
        float s = a0 + a1;
        if (k < cnt) s += p[(size_t)k * DD];
        g_sum[b * DD + col] = s;

        red[tid] = s * s;
        __syncthreads();
        if (tid < 96) red[tid] += red[tid + 96];
        __syncthreads();
        if (tid < 48) red[tid] += red[tid + 48];
        __syncthreads();
        if (tid < 32) {
            float v = red[tid] + (tid < 16 ? red[tid + 32] : 0.f);
#pragma unroll
            for (int off = 16; off > 0; off >>= 1)
                v += __shfl_xor_sync(0xFFFFFFFFu, v, off);
            if (tid == 0) g_sqpart[b * 4 + g] = v;
        }
    }

    grid_barrier();

    // ---- Phase 3: finalize, warp-per-row (R11 pattern: v[6] held, ~64 regs),
    // fractional 7-8 row windows per warp, DESCENDING. One preload sync, then
    // fully independent warps. All warps at the same fractional position ->
    // coherent frontier -> second x read mostly L2 hits (~75-85 MB saved).
    {
#pragma unroll
        for (int k = 0; k < 8; k++) {
            const int idx = tid + k * NT;               // 0..1535
            reinterpret_cast<float4*>(s_buf)[idx] =
                reinterpret_cast<const float4*>(g_sum)[idx];
        }
        if (tid < BB) {
            const float sq = (g_sqpart[tid * 4 + 0] + g_sqpart[tid * 4 + 1])
                           + (g_sqpart[tid * 4 + 2] + g_sqpart[tid * 4 + 3]);
            const double denom = (double)DD * (double)DD
                               * (double)LL * (double)LL * (double)LL * (double)LL;
            s_coef[tid] = (float)((double)sq / denom);
        }
        __syncthreads();   // the only phase-3 sync

        const int wg = bid * 6 + warp;        // 0..4439
        const int b  = wg / WPBATCH;
        const int wb = wg - b * WPBATCH;      // 0..554
        const int r0 = (wb * LL) / WPBATCH;
        const int r1 = ((wb + 1) * LL) / WPBATCH;   // 7-8 rows

        const float coef = s_coef[b];
        const float* xb = x + ((size_t)b << 12) * DD;
        float* ob = out + ((size_t)b << 12) * DD;

        for (int l = r1 - 1; l >= r0; l--) {        // descending
            const float4* xp = reinterpret_cast<const float4*>(xb + (size_t)l * DD) + lane;
            float4 v[6];
            float dot = 0.f;
#pragma unroll
            for (int i = 0; i < 6; i++) {
                v[i] = xp[i * 32];
                float4 m = s_buf[b][lane + i * 32];
                dot += v[i].x * m.x + v[i].y * m.y + v[i].z * m.z + v[i].w * m.w;
            }
#pragma unroll
            for (int off = 16; off > 0; off >>= 1)
                dot += __shfl_xor_sync(0xFFFFFFFFu, dot, off);

            const float y2 = dot * coef;
            const float a  = alpha[l];

            float4* op = reinterpret_cast<float4*>(ob + (size_t)l * DD) + lane;
#pragma unroll
            for (int i = 0; i < 6; i++) {
                float4 o;
                o.x = a + y2 * v[i].x;
                o.y = a + y2 * v[i].y;
                o.z = a + y2 * v[i].z;
                o.w = a + y2 * v[i].w;
                op[i * 32] = o;
            }
        }
    }
}

extern "C" void kernel_launch(void* const* d_in, const int* in_sizes, int n_in,
                              void* d_out, int out_size) {
    const float* x     = (const float*)d_in[0];   // [8, 4096, 768] f32
    const float* alpha = (const float*)d_in[1];   // [4096, 1] f32
    float* out = (float*)d_out;                   // [8, 4096, 768] f32

    fused_kernel<<<NB, NT>>>(x, alpha, out);
}